// round 11
// baseline (speedup 1.0000x reference)
#include <cuda_runtime.h>
#include <math.h>

#define NN 50000
#define EE 800000
// feature dims
// h: 64, edge_attr: 16, radial: 16 (4x4), kv_in = 96, kv_out = 128

// ---------------- scratch (device globals; no allocation) ----------------
__device__ float g_Q[NN * 64];       // q = h@Wq + bq per node
__device__ float g_Hkv[NN * 128];    // h@Wkv[16:80] + bkv per node (interleaved k/v cols)
__device__ float g_vT[64 * EE];      // v transposed [j][e] for coalescing
__device__ float g_cv[EE * 4];       // silu(v@W1+b1)@W2 per edge (without att factor)
__device__ float g_sumsq[16];
__device__ float g_invn[16];
__device__ float g_segmax[NN];
__device__ float g_segsum[NN];

// ---------------- helpers ----------------
__device__ __forceinline__ void atomicMaxF(float* addr, float v) {
    if (v >= 0.0f) atomicMax((int*)addr, __float_as_int(v));
    else           atomicMin((unsigned int*)addr, __float_as_uint(v));
}

__device__ __forceinline__ void redAdd4(float* p, float a, float b, float c, float d) {
    asm volatile("red.global.add.v4.f32 [%0], {%1, %2, %3, %4};"
                 :: "l"(p), "f"(a), "f"(b), "f"(c), "f"(d) : "memory");
}

// ---------------- K0: init ----------------
__global__ void k_init(const float* __restrict__ h, const float* __restrict__ coord,
                       float* __restrict__ out) {
    int i = blockIdx.x * blockDim.x + threadIdx.x;
    if (i < NN * 64) out[i] = h[i];                 // h_out = h
    if (i < NN * 12) out[NN * 64 + i] = coord[i];   // coord_out = coord
    if (i < NN) { g_segmax[i] = -INFINITY; g_segsum[i] = 0.0f; }
    if (i < 16) g_sumsq[i] = 0.0f;
}

// ---------------- K1: global sum of radial^2 ----------------
__global__ void k_sumsq(const float* __restrict__ coord,
                        const int* __restrict__ row, const int* __restrict__ col) {
    __shared__ float s[16];
    if (threadIdx.x < 16) s[threadIdx.x] = 0.0f;
    __syncthreads();

    float acc[16];
#pragma unroll
    for (int t = 0; t < 16; t++) acc[t] = 0.0f;

    int stride = gridDim.x * blockDim.x;
    for (int e = blockIdx.x * blockDim.x + threadIdx.x; e < EE; e += stride) {
        int r = row[e], c = col[e];
        const float4* pr = (const float4*)(coord + r * 12);
        const float4* pc = (const float4*)(coord + c * 12);
        float4 u0 = pr[0], u1 = pr[1], u2 = pr[2];
        float4 w0 = pc[0], w1 = pc[1], w2 = pc[2];
        float d[12] = {u0.x - w0.x, u0.y - w0.y, u0.z - w0.z, u0.w - w0.w,
                       u1.x - w1.x, u1.y - w1.y, u1.z - w1.z, u1.w - w1.w,
                       u2.x - w2.x, u2.y - w2.y, u2.z - w2.z, u2.w - w2.w};
#pragma unroll
        for (int a = 0; a < 4; a++)
#pragma unroll
            for (int b = 0; b < 4; b++) {
                float rv = d[a*3+0]*d[b*3+0] + d[a*3+1]*d[b*3+1] + d[a*3+2]*d[b*3+2];
                acc[a*4+b] = fmaf(rv, rv, acc[a*4+b]);
            }
    }
#pragma unroll
    for (int t = 0; t < 16; t++) atomicAdd(&s[t], acc[t]);
    __syncthreads();
    if (threadIdx.x < 16) atomicAdd(&g_sumsq[threadIdx.x], s[threadIdx.x]);
}

// ---------------- K2: invnorm ----------------
__global__ void k_norm() {
    int i = threadIdx.x;
    if (i < 16) g_invn[i] = 1.0f / fmaxf(sqrtf(g_sumsq[i]), 1e-12f);
}

// ---------------- K3: per-node projections ----------------
// Q[n][j]   = bq[j]  + sum_i h[n][i] * Wq[i][j]              (j < 64)
// Hkv[n][j] = bkv[j] + sum_i h[n][i] * Wkv[16+i][j]          (j < 128)
__global__ __launch_bounds__(128) void k_node(const float* __restrict__ h,
                                              const float* __restrict__ Wq,
                                              const float* __restrict__ bq,
                                              const float* __restrict__ Wkv,
                                              const float* __restrict__ bkv) {
    __shared__ float sWm[64 * 128];
    __shared__ float sBkv[128];
    __shared__ float sBq[64];
    __shared__ float sh[64];

    int tid = threadIdx.x;
    for (int i = tid; i < 64 * 128; i += 128) sWm[i] = Wkv[16 * 128 + i];
    if (tid < 128) sBkv[tid] = bkv[tid];
    if (tid < 64)  sBq[tid]  = bq[tid];
    __syncthreads();

    for (int n = blockIdx.x; n < NN; n += gridDim.x) {
        if (tid < 64) sh[tid] = h[n * 64 + tid];
        __syncthreads();
        float accH = sBkv[tid];
        float accQ = (tid < 64) ? sBq[tid] : 0.0f;
#pragma unroll 8
        for (int i = 0; i < 64; i++) {
            float hi = sh[i];
            accH = fmaf(hi, sWm[i * 128 + tid], accH);
            if (tid < 64) accQ = fmaf(hi, __ldg(Wq + i * 64 + tid), accQ);
        }
        g_Hkv[n * 128 + tid] = accH;
        if (tid < 64) g_Q[n * 64 + tid] = accQ;
        __syncthreads();
    }
}

// ---------------- K4: per-edge main kernel ----------------
__global__ __launch_bounds__(128, 4) void k_edge(const float* __restrict__ coord,
                                                 const int* __restrict__ row,
                                                 const int* __restrict__ col,
                                                 const float* __restrict__ eattr,
                                                 const float* __restrict__ Wkv,
                                                 const float* __restrict__ W1,
                                                 const float* __restrict__ b1,
                                                 const float* __restrict__ W2,
                                                 float* __restrict__ att) {
    // transposed weight slices: rows of 16 contiguous floats per output col
    __shared__ float sWr[128 * 16];   // sWr[j2*16+i] = Wkv[i][j2]        (radial rows 0..15)
    __shared__ float sWe[128 * 16];   // sWe[j2*16+i] = Wkv[80+i][j2]     (edge_attr rows)
    __shared__ float sW1[64 * 64];    // sW1[m*64+j] = W1[j][m]
    __shared__ float sW2[64 * 4];
    __shared__ float sb1[64];
    __shared__ float sInv[16];

    int tid = threadIdx.x;
    for (int idx = tid; idx < 128 * 16; idx += 128) {
        int j2 = idx >> 4, i = idx & 15;
        sWr[idx] = Wkv[i * 128 + j2];
        sWe[idx] = Wkv[(80 + i) * 128 + j2];
    }
    for (int idx = tid; idx < 64 * 64; idx += 128) {
        int m = idx >> 6, j = idx & 63;
        sW1[idx] = W1[j * 64 + m];
    }
    for (int idx = tid; idx < 256; idx += 128) sW2[idx] = W2[idx];
    if (tid < 64) sb1[tid] = b1[tid];
    if (tid < 16) sInv[tid] = g_invn[tid];
    __syncthreads();

    int stride = gridDim.x * blockDim.x;
    for (int e = blockIdx.x * blockDim.x + tid; e < EE; e += stride) {
        int r = row[e], c = col[e];

        // radial (normalized)
        const float4* pr = (const float4*)(coord + r * 12);
        const float4* pc = (const float4*)(coord + c * 12);
        float4 u0 = pr[0], u1 = pr[1], u2 = pr[2];
        float4 w0 = pc[0], w1 = pc[1], w2 = pc[2];
        float d[12] = {u0.x - w0.x, u0.y - w0.y, u0.z - w0.z, u0.w - w0.w,
                       u1.x - w1.x, u1.y - w1.y, u1.z - w1.z, u1.w - w1.w,
                       u2.x - w2.x, u2.y - w2.y, u2.z - w2.z, u2.w - w2.w};
        float rad[16];
#pragma unroll
        for (int a = 0; a < 4; a++)
#pragma unroll
            for (int b = 0; b < 4; b++)
                rad[a*4+b] = (d[a*3+0]*d[b*3+0] + d[a*3+1]*d[b*3+1] + d[a*3+2]*d[b*3+2])
                             * sInv[a*4+b];

        float eav[16];
        {
            const float4* pe = (const float4*)(eattr + e * 16);
            float4 e0 = pe[0], e1 = pe[1], e2 = pe[2], e3 = pe[3];
            eav[0]=e0.x; eav[1]=e0.y; eav[2]=e0.z; eav[3]=e0.w;
            eav[4]=e1.x; eav[5]=e1.y; eav[6]=e1.z; eav[7]=e1.w;
            eav[8]=e2.x; eav[9]=e2.y; eav[10]=e2.z; eav[11]=e2.w;
            eav[12]=e3.x; eav[13]=e3.y; eav[14]=e3.z; eav[15]=e3.w;
        }

        const float*  qp = g_Q + r * 64;
        const float2* hp = (const float2*)(g_Hkv + c * 128);

        float alpha = 0.0f;
#pragma unroll 2
        for (int j = 0; j < 64; j++) {
            const float* wrk = sWr + 32 * j;   // cols 2j (k) and 2j+1 (v)
            const float* wek = sWe + 32 * j;
            float kk = 0.0f, vv = 0.0f;
#pragma unroll
            for (int i = 0; i < 16; i++) {
                kk = fmaf(rad[i], wrk[i],      kk);
                vv = fmaf(rad[i], wrk[16 + i], vv);
            }
#pragma unroll
            for (int i = 0; i < 16; i++) {
                kk = fmaf(eav[i], wek[i],      kk);
                vv = fmaf(eav[i], wek[16 + i], vv);
            }
            float2 hv = hp[j];
            kk += hv.x;
            vv += hv.y;
            alpha = fmaf(__ldg(qp + j), kk, alpha);
            g_vT[j * EE + e] = vv;             // coalesced across warp
        }

        att[e] = alpha;
        atomicMaxF(&g_segmax[r], alpha);

        // silu MLP: cv = silu(v@W1 + b1) @ W2   (v reloaded; L2/L1 hits — just written)
        float vr[64];
#pragma unroll
        for (int j = 0; j < 64; j++) vr[j] = g_vT[j * EE + e];

        float cv0 = 0.0f, cv1 = 0.0f, cv2 = 0.0f, cv3 = 0.0f;
#pragma unroll 2
        for (int m = 0; m < 64; m++) {
            const float* wm = sW1 + 64 * m;
            float t = sb1[m];
#pragma unroll
            for (int j = 0; j < 64; j++) t = fmaf(vr[j], wm[j], t);
            float s = __fdividef(t, 1.0f + __expf(-t));   // silu
            cv0 = fmaf(s, sW2[4 * m + 0], cv0);
            cv1 = fmaf(s, sW2[4 * m + 1], cv1);
            cv2 = fmaf(s, sW2[4 * m + 2], cv2);
            cv3 = fmaf(s, sW2[4 * m + 3], cv3);
        }
        *(float4*)(g_cv + 4 * e) = make_float4(cv0, cv1, cv2, cv3);
    }
}

// ---------------- K5: segment softmax (exp + sum) ----------------
__global__ void k_exp(const int* __restrict__ row, float* __restrict__ att) {
    int e = blockIdx.x * blockDim.x + threadIdx.x;
    if (e >= EE) return;
    int r = row[e];
    float ex = __expf(att[e] - g_segmax[r]);
    att[e] = ex;
    atomicAdd(&g_segsum[r], ex);
}

// ---------------- K6: aggregation ----------------
__global__ void k_agg(const float* __restrict__ coord,
                      const int* __restrict__ row, const int* __restrict__ col,
                      float* __restrict__ out) {
    int e = blockIdx.x * blockDim.x + threadIdx.x;
    if (e >= EE) return;
    int r = row[e], c = col[e];

    float* att = out + NN * 76;
    float a = att[e] / g_segsum[r];
    att[e] = a;

    // h_out[r] += a * v
    float* hout = out + r * 64;
#pragma unroll
    for (int j = 0; j < 64; j += 4) {
        float x0 = a * g_vT[(j + 0) * EE + e];
        float x1 = a * g_vT[(j + 1) * EE + e];
        float x2 = a * g_vT[(j + 2) * EE + e];
        float x3 = a * g_vT[(j + 3) * EE + e];
        redAdd4(hout + j, x0, x1, x2, x3);
    }

    // coord_out[r] += coord_diff * (a * cv)
    float4 cv = *(const float4*)(g_cv + 4 * e);
    float s0 = a * cv.x, s1 = a * cv.y, s2 = a * cv.z, s3 = a * cv.w;

    const float4* pr = (const float4*)(coord + r * 12);
    const float4* pc = (const float4*)(coord + c * 12);
    float4 u0 = pr[0], u1 = pr[1], u2 = pr[2];
    float4 w0 = pc[0], w1 = pc[1], w2 = pc[2];
    float d0 = u0.x - w0.x, d1 = u0.y - w0.y, d2  = u0.z - w0.z, d3  = u0.w - w0.w;
    float d4 = u1.x - w1.x, d5 = u1.y - w1.y, d6  = u1.z - w1.z, d7  = u1.w - w1.w;
    float d8 = u2.x - w2.x, d9 = u2.y - w2.y, d10 = u2.z - w2.z, d11 = u2.w - w2.w;

    float* cout = out + NN * 64 + r * 12;
    redAdd4(cout + 0, d0 * s0, d1 * s0, d2 * s0,  d3 * s1);
    redAdd4(cout + 4, d4 * s1, d5 * s1, d6 * s2,  d7 * s2);
    redAdd4(cout + 8, d8 * s2, d9 * s3, d10 * s3, d11 * s3);
}

// ---------------- launch ----------------
extern "C" void kernel_launch(void* const* d_in, const int* in_sizes, int n_in,
                              void* d_out, int out_size) {
    const float* h     = (const float*)d_in[0];
    const float* coord = (const float*)d_in[1];
    const int*   row   = (const int*)  d_in[2];
    const int*   col   = (const int*)  d_in[3];
    const float* eattr = (const float*)d_in[4];
    const float* Wq    = (const float*)d_in[5];
    const float* bq    = (const float*)d_in[6];
    const float* Wkv   = (const float*)d_in[7];
    const float* bkv   = (const float*)d_in[8];
    const float* W1    = (const float*)d_in[9];
    const float* b1    = (const float*)d_in[10];
    const float* W2    = (const float*)d_in[11];
    float* out = (float*)d_out;
    float* att = out + NN * 76;

    k_init <<<(NN * 64 + 255) / 256, 256>>>(h, coord, out);
    k_sumsq<<<1184, 256>>>(coord, row, col);
    k_norm <<<1, 16>>>();
    k_node <<<592, 128>>>(h, Wq, bq, Wkv, bkv);
    k_edge <<<1184, 128>>>(coord, row, col, eattr, Wkv, W1, b1, W2, att);
    k_exp  <<<(EE + 255) / 256, 256>>>(row, att);
    k_agg  <<<(EE + 255) / 256, 256>>>(coord, row, col, out);
}

// round 12
// speedup vs baseline: 1.0020x; 1.0020x over previous
#include <cuda_runtime.h>
#include <math.h>

#define NN 50000
#define EE 800000
// feature dims
// h: 64, edge_attr: 16, radial: 16 (4x4), kv_in = 96, kv_out = 128

// ---------------- scratch (device globals; no allocation) ----------------
__device__ float g_Q[NN * 64];       // q = h@Wq + bq per node
__device__ float g_Hkv[NN * 128];    // h@Wkv[16:80] + bkv per node (interleaved k/v cols)
__device__ float g_vT[64 * EE];      // v transposed [j][e] for coalescing
__device__ float g_cv[EE * 4];       // silu(v@W1+b1)@W2 per edge (without att factor)
__device__ float g_sumsq[16];
__device__ float g_invn[16];
__device__ float g_segmax[NN];
__device__ float g_segsum[NN];

// ---------------- helpers ----------------
__device__ __forceinline__ void atomicMaxF(float* addr, float v) {
    if (v >= 0.0f) atomicMax((int*)addr, __float_as_int(v));
    else           atomicMin((unsigned int*)addr, __float_as_uint(v));
}

__device__ __forceinline__ void redAdd4(float* p, float a, float b, float c, float d) {
    asm volatile("red.global.add.v4.f32 [%0], {%1, %2, %3, %4};"
                 :: "l"(p), "f"(a), "f"(b), "f"(c), "f"(d) : "memory");
}

// ---------------- K0: init ----------------
__global__ void k_init(const float* __restrict__ h, const float* __restrict__ coord,
                       float* __restrict__ out) {
    int i = blockIdx.x * blockDim.x + threadIdx.x;
    if (i < NN * 64) out[i] = h[i];                 // h_out = h
    if (i < NN * 12) out[NN * 64 + i] = coord[i];   // coord_out = coord
    if (i < NN) { g_segmax[i] = -INFINITY; g_segsum[i] = 0.0f; }
    if (i < 16) g_sumsq[i] = 0.0f;
}

// ---------------- K1: global sum of radial^2 ----------------
__global__ void k_sumsq(const float* __restrict__ coord,
                        const int* __restrict__ row, const int* __restrict__ col) {
    __shared__ float s[16];
    if (threadIdx.x < 16) s[threadIdx.x] = 0.0f;
    __syncthreads();

    float acc[16];
#pragma unroll
    for (int t = 0; t < 16; t++) acc[t] = 0.0f;

    int stride = gridDim.x * blockDim.x;
    for (int e = blockIdx.x * blockDim.x + threadIdx.x; e < EE; e += stride) {
        int r = row[e], c = col[e];
        const float4* pr = (const float4*)(coord + r * 12);
        const float4* pc = (const float4*)(coord + c * 12);
        float4 u0 = pr[0], u1 = pr[1], u2 = pr[2];
        float4 w0 = pc[0], w1 = pc[1], w2 = pc[2];
        float d[12] = {u0.x - w0.x, u0.y - w0.y, u0.z - w0.z, u0.w - w0.w,
                       u1.x - w1.x, u1.y - w1.y, u1.z - w1.z, u1.w - w1.w,
                       u2.x - w2.x, u2.y - w2.y, u2.z - w2.z, u2.w - w2.w};
#pragma unroll
        for (int a = 0; a < 4; a++)
#pragma unroll
            for (int b = 0; b < 4; b++) {
                float rv = d[a*3+0]*d[b*3+0] + d[a*3+1]*d[b*3+1] + d[a*3+2]*d[b*3+2];
                acc[a*4+b] = fmaf(rv, rv, acc[a*4+b]);
            }
    }
#pragma unroll
    for (int t = 0; t < 16; t++) atomicAdd(&s[t], acc[t]);
    __syncthreads();
    if (threadIdx.x < 16) atomicAdd(&g_sumsq[threadIdx.x], s[threadIdx.x]);
}

// ---------------- K2: invnorm ----------------
__global__ void k_norm() {
    int i = threadIdx.x;
    if (i < 16) g_invn[i] = 1.0f / fmaxf(sqrtf(g_sumsq[i]), 1e-12f);
}

// ---------------- K3: per-node projections ----------------
// Q[n][j]   = bq[j]  + sum_i h[n][i] * Wq[i][j]              (j < 64)
// Hkv[n][j] = bkv[j] + sum_i h[n][i] * Wkv[16+i][j]          (j < 128)
__global__ __launch_bounds__(128) void k_node(const float* __restrict__ h,
                                              const float* __restrict__ Wq,
                                              const float* __restrict__ bq,
                                              const float* __restrict__ Wkv,
                                              const float* __restrict__ bkv) {
    __shared__ float sWm[64 * 128];
    __shared__ float sBkv[128];
    __shared__ float sBq[64];
    __shared__ float sh[64];

    int tid = threadIdx.x;
    for (int i = tid; i < 64 * 128; i += 128) sWm[i] = Wkv[16 * 128 + i];
    if (tid < 128) sBkv[tid] = bkv[tid];
    if (tid < 64)  sBq[tid]  = bq[tid];
    __syncthreads();

    for (int n = blockIdx.x; n < NN; n += gridDim.x) {
        if (tid < 64) sh[tid] = h[n * 64 + tid];
        __syncthreads();
        float accH = sBkv[tid];
        float accQ = (tid < 64) ? sBq[tid] : 0.0f;
#pragma unroll 8
        for (int i = 0; i < 64; i++) {
            float hi = sh[i];
            accH = fmaf(hi, sWm[i * 128 + tid], accH);
            if (tid < 64) accQ = fmaf(hi, __ldg(Wq + i * 64 + tid), accQ);
        }
        g_Hkv[n * 128 + tid] = accH;
        if (tid < 64) g_Q[n * 64 + tid] = accQ;
        __syncthreads();
    }
}

// ---------------- K4: per-edge main kernel ----------------
__global__ __launch_bounds__(128, 4) void k_edge(const float* __restrict__ coord,
                                                 const int* __restrict__ row,
                                                 const int* __restrict__ col,
                                                 const float* __restrict__ eattr,
                                                 const float* __restrict__ Wkv,
                                                 const float* __restrict__ W1,
                                                 const float* __restrict__ b1,
                                                 const float* __restrict__ W2,
                                                 float* __restrict__ att) {
    // transposed weight slices: rows of 16 contiguous floats per output col
    __shared__ float sWr[128 * 16];   // sWr[j2*16+i] = Wkv[i][j2]        (radial rows 0..15)
    __shared__ float sWe[128 * 16];   // sWe[j2*16+i] = Wkv[80+i][j2]     (edge_attr rows)
    __shared__ float sW1[64 * 64];    // sW1[m*64+j] = W1[j][m]
    __shared__ float sW2[64 * 4];
    __shared__ float sb1[64];
    __shared__ float sInv[16];

    int tid = threadIdx.x;
    for (int idx = tid; idx < 128 * 16; idx += 128) {
        int j2 = idx >> 4, i = idx & 15;
        sWr[idx] = Wkv[i * 128 + j2];
        sWe[idx] = Wkv[(80 + i) * 128 + j2];
    }
    for (int idx = tid; idx < 64 * 64; idx += 128) {
        int m = idx >> 6, j = idx & 63;
        sW1[idx] = W1[j * 64 + m];
    }
    for (int idx = tid; idx < 256; idx += 128) sW2[idx] = W2[idx];
    if (tid < 64) sb1[tid] = b1[tid];
    if (tid < 16) sInv[tid] = g_invn[tid];
    __syncthreads();

    int stride = gridDim.x * blockDim.x;
    for (int e = blockIdx.x * blockDim.x + tid; e < EE; e += stride) {
        int r = row[e], c = col[e];

        // radial (normalized)
        const float4* pr = (const float4*)(coord + r * 12);
        const float4* pc = (const float4*)(coord + c * 12);
        float4 u0 = pr[0], u1 = pr[1], u2 = pr[2];
        float4 w0 = pc[0], w1 = pc[1], w2 = pc[2];
        float d[12] = {u0.x - w0.x, u0.y - w0.y, u0.z - w0.z, u0.w - w0.w,
                       u1.x - w1.x, u1.y - w1.y, u1.z - w1.z, u1.w - w1.w,
                       u2.x - w2.x, u2.y - w2.y, u2.z - w2.z, u2.w - w2.w};
        float rad[16];
#pragma unroll
        for (int a = 0; a < 4; a++)
#pragma unroll
            for (int b = 0; b < 4; b++)
                rad[a*4+b] = (d[a*3+0]*d[b*3+0] + d[a*3+1]*d[b*3+1] + d[a*3+2]*d[b*3+2])
                             * sInv[a*4+b];

        float eav[16];
        {
            const float4* pe = (const float4*)(eattr + e * 16);
            float4 e0 = pe[0], e1 = pe[1], e2 = pe[2], e3 = pe[3];
            eav[0]=e0.x; eav[1]=e0.y; eav[2]=e0.z; eav[3]=e0.w;
            eav[4]=e1.x; eav[5]=e1.y; eav[6]=e1.z; eav[7]=e1.w;
            eav[8]=e2.x; eav[9]=e2.y; eav[10]=e2.z; eav[11]=e2.w;
            eav[12]=e3.x; eav[13]=e3.y; eav[14]=e3.z; eav[15]=e3.w;
        }

        const float*  qp = g_Q + r * 64;
        const float2* hp = (const float2*)(g_Hkv + c * 128);

        float alpha = 0.0f;
#pragma unroll 2
        for (int j = 0; j < 64; j++) {
            const float* wrk = sWr + 32 * j;   // cols 2j (k) and 2j+1 (v)
            const float* wek = sWe + 32 * j;
            float kk = 0.0f, vv = 0.0f;
#pragma unroll
            for (int i = 0; i < 16; i++) {
                kk = fmaf(rad[i], wrk[i],      kk);
                vv = fmaf(rad[i], wrk[16 + i], vv);
            }
#pragma unroll
            for (int i = 0; i < 16; i++) {
                kk = fmaf(eav[i], wek[i],      kk);
                vv = fmaf(eav[i], wek[16 + i], vv);
            }
            float2 hv = hp[j];
            kk += hv.x;
            vv += hv.y;
            alpha = fmaf(__ldg(qp + j), kk, alpha);
            g_vT[j * EE + e] = vv;             // coalesced across warp
        }

        att[e] = alpha;
        atomicMaxF(&g_segmax[r], alpha);

        // silu MLP: cv = silu(v@W1 + b1) @ W2   (v reloaded; L2/L1 hits — just written)
        float vr[64];
#pragma unroll
        for (int j = 0; j < 64; j++) vr[j] = g_vT[j * EE + e];

        float cv0 = 0.0f, cv1 = 0.0f, cv2 = 0.0f, cv3 = 0.0f;
#pragma unroll 2
        for (int m = 0; m < 64; m++) {
            const float* wm = sW1 + 64 * m;
            float t = sb1[m];
#pragma unroll
            for (int j = 0; j < 64; j++) t = fmaf(vr[j], wm[j], t);
            float s = __fdividef(t, 1.0f + __expf(-t));   // silu
            cv0 = fmaf(s, sW2[4 * m + 0], cv0);
            cv1 = fmaf(s, sW2[4 * m + 1], cv1);
            cv2 = fmaf(s, sW2[4 * m + 2], cv2);
            cv3 = fmaf(s, sW2[4 * m + 3], cv3);
        }
        *(float4*)(g_cv + 4 * e) = make_float4(cv0, cv1, cv2, cv3);
    }
}

// ---------------- K5: segment softmax (exp + sum) ----------------
__global__ void k_exp(const int* __restrict__ row, float* __restrict__ att) {
    int e = blockIdx.x * blockDim.x + threadIdx.x;
    if (e >= EE) return;
    int r = row[e];
    float ex = __expf(att[e] - g_segmax[r]);
    att[e] = ex;
    atomicAdd(&g_segsum[r], ex);
}

// ---------------- K6: aggregation ----------------
__global__ void k_agg(const float* __restrict__ coord,
                      const int* __restrict__ row, const int* __restrict__ col,
                      float* __restrict__ out) {
    int e = blockIdx.x * blockDim.x + threadIdx.x;
    if (e >= EE) return;
    int r = row[e], c = col[e];

    float* att = out + NN * 76;
    float a = att[e] / g_segsum[r];
    att[e] = a;

    // h_out[r] += a * v
    float* hout = out + r * 64;
#pragma unroll
    for (int j = 0; j < 64; j += 4) {
        float x0 = a * g_vT[(j + 0) * EE + e];
        float x1 = a * g_vT[(j + 1) * EE + e];
        float x2 = a * g_vT[(j + 2) * EE + e];
        float x3 = a * g_vT[(j + 3) * EE + e];
        redAdd4(hout + j, x0, x1, x2, x3);
    }

    // coord_out[r] += coord_diff * (a * cv)
    float4 cv = *(const float4*)(g_cv + 4 * e);
    float s0 = a * cv.x, s1 = a * cv.y, s2 = a * cv.z, s3 = a * cv.w;

    const float4* pr = (const float4*)(coord + r * 12);
    const float4* pc = (const float4*)(coord + c * 12);
    float4 u0 = pr[0], u1 = pr[1], u2 = pr[2];
    float4 w0 = pc[0], w1 = pc[1], w2 = pc[2];
    float d0 = u0.x - w0.x, d1 = u0.y - w0.y, d2  = u0.z - w0.z, d3  = u0.w - w0.w;
    float d4 = u1.x - w1.x, d5 = u1.y - w1.y, d6  = u1.z - w1.z, d7  = u1.w - w1.w;
    float d8 = u2.x - w2.x, d9 = u2.y - w2.y, d10 = u2.z - w2.z, d11 = u2.w - w2.w;

    float* cout = out + NN * 64 + r * 12;
    redAdd4(cout + 0, d0 * s0, d1 * s0, d2 * s0,  d3 * s1);
    redAdd4(cout + 4, d4 * s1, d5 * s1, d6 * s2,  d7 * s2);
    redAdd4(cout + 8, d8 * s2, d9 * s3, d10 * s3, d11 * s3);
}

// ---------------- launch ----------------
extern "C" void kernel_launch(void* const* d_in, const int* in_sizes, int n_in,
                              void* d_out, int out_size) {
    const float* h     = (const float*)d_in[0];
    const float* coord = (const float*)d_in[1];
    const int*   row   = (const int*)  d_in[2];
    const int*   col   = (const int*)  d_in[3];
    const float* eattr = (const float*)d_in[4];
    const float* Wq    = (const float*)d_in[5];
    const float* bq    = (const float*)d_in[6];
    const float* Wkv   = (const float*)d_in[7];
    const float* bkv   = (const float*)d_in[8];
    const float* W1    = (const float*)d_in[9];
    const float* b1    = (const float*)d_in[10];
    const float* W2    = (const float*)d_in[11];
    float* out = (float*)d_out;
    float* att = out + NN * 76;

    k_init <<<(NN * 64 + 255) / 256, 256>>>(h, coord, out);
    k_sumsq<<<1184, 256>>>(coord, row, col);
    k_norm <<<1, 16>>>();
    k_node <<<592, 128>>>(h, Wq, bq, Wkv, bkv);
    k_edge <<<1184, 128>>>(coord, row, col, eattr, Wkv, W1, b1, W2, att);
    k_exp  <<<(EE + 255) / 256, 256>>>(row, att);
    k_agg  <<<(EE + 255) / 256, 256>>>(coord, row, col, out);
}

// round 14
// speedup vs baseline: 1.0024x; 1.0003x over previous
#include <cuda_runtime.h>
#include <math.h>

#define NN 50000
#define EE 800000
// feature dims
// h: 64, edge_attr: 16, radial: 16 (4x4), kv_in = 96, kv_out = 128

// ---------------- scratch (device globals; no allocation) ----------------
__device__ float g_Q[NN * 64];       // q = h@Wq + bq per node
__device__ float g_Hkv[NN * 128];    // h@Wkv[16:80] + bkv per node (interleaved k/v cols)
__device__ float g_vT[64 * EE];      // v transposed [j][e] for coalescing
__device__ float g_cv[EE * 4];       // silu(v@W1+b1)@W2 per edge (without att factor)
__device__ float g_sumsq[16];
__device__ float g_invn[16];
__device__ float g_segmax[NN];
__device__ float g_segsum[NN];

// ---------------- helpers ----------------
__device__ __forceinline__ void atomicMaxF(float* addr, float v) {
    if (v >= 0.0f) atomicMax((int*)addr, __float_as_int(v));
    else           atomicMin((unsigned int*)addr, __float_as_uint(v));
}

__device__ __forceinline__ void redAdd4(float* p, float a, float b, float c, float d) {
    asm volatile("red.global.add.v4.f32 [%0], {%1, %2, %3, %4};"
                 :: "l"(p), "f"(a), "f"(b), "f"(c), "f"(d) : "memory");
}

// ---------------- K0: init ----------------
__global__ void k_init(const float* __restrict__ h, const float* __restrict__ coord,
                       float* __restrict__ out) {
    int i = blockIdx.x * blockDim.x + threadIdx.x;
    if (i < NN * 64) out[i] = h[i];                 // h_out = h
    if (i < NN * 12) out[NN * 64 + i] = coord[i];   // coord_out = coord
    if (i < NN) { g_segmax[i] = -INFINITY; g_segsum[i] = 0.0f; }
    if (i < 16) g_sumsq[i] = 0.0f;
}

// ---------------- K1: global sum of radial^2 ----------------
__global__ void k_sumsq(const float* __restrict__ coord,
                        const int* __restrict__ row, const int* __restrict__ col) {
    __shared__ float s[16];
    if (threadIdx.x < 16) s[threadIdx.x] = 0.0f;
    __syncthreads();

    float acc[16];
#pragma unroll
    for (int t = 0; t < 16; t++) acc[t] = 0.0f;

    int stride = gridDim.x * blockDim.x;
    for (int e = blockIdx.x * blockDim.x + threadIdx.x; e < EE; e += stride) {
        int r = row[e], c = col[e];
        const float4* pr = (const float4*)(coord + r * 12);
        const float4* pc = (const float4*)(coord + c * 12);
        float4 u0 = pr[0], u1 = pr[1], u2 = pr[2];
        float4 w0 = pc[0], w1 = pc[1], w2 = pc[2];
        float d[12] = {u0.x - w0.x, u0.y - w0.y, u0.z - w0.z, u0.w - w0.w,
                       u1.x - w1.x, u1.y - w1.y, u1.z - w1.z, u1.w - w1.w,
                       u2.x - w2.x, u2.y - w2.y, u2.z - w2.z, u2.w - w2.w};
#pragma unroll
        for (int a = 0; a < 4; a++)
#pragma unroll
            for (int b = 0; b < 4; b++) {
                float rv = d[a*3+0]*d[b*3+0] + d[a*3+1]*d[b*3+1] + d[a*3+2]*d[b*3+2];
                acc[a*4+b] = fmaf(rv, rv, acc[a*4+b]);
            }
    }
#pragma unroll
    for (int t = 0; t < 16; t++) atomicAdd(&s[t], acc[t]);
    __syncthreads();
    if (threadIdx.x < 16) atomicAdd(&g_sumsq[threadIdx.x], s[threadIdx.x]);
}

// ---------------- K2: invnorm ----------------
__global__ void k_norm() {
    int i = threadIdx.x;
    if (i < 16) g_invn[i] = 1.0f / fmaxf(sqrtf(g_sumsq[i]), 1e-12f);
}

// ---------------- K3: per-node projections ----------------
// Q[n][j]   = bq[j]  + sum_i h[n][i] * Wq[i][j]              (j < 64)
// Hkv[n][j] = bkv[j] + sum_i h[n][i] * Wkv[16+i][j]          (j < 128)
__global__ __launch_bounds__(128) void k_node(const float* __restrict__ h,
                                              const float* __restrict__ Wq,
                                              const float* __restrict__ bq,
                                              const float* __restrict__ Wkv,
                                              const float* __restrict__ bkv) {
    __shared__ float sWm[64 * 128];
    __shared__ float sBkv[128];
    __shared__ float sBq[64];
    __shared__ float sh[64];

    int tid = threadIdx.x;
    for (int i = tid; i < 64 * 128; i += 128) sWm[i] = Wkv[16 * 128 + i];
    if (tid < 128) sBkv[tid] = bkv[tid];
    if (tid < 64)  sBq[tid]  = bq[tid];
    __syncthreads();

    for (int n = blockIdx.x; n < NN; n += gridDim.x) {
        if (tid < 64) sh[tid] = h[n * 64 + tid];
        __syncthreads();
        float accH = sBkv[tid];
        float accQ = (tid < 64) ? sBq[tid] : 0.0f;
#pragma unroll 8
        for (int i = 0; i < 64; i++) {
            float hi = sh[i];
            accH = fmaf(hi, sWm[i * 128 + tid], accH);
            if (tid < 64) accQ = fmaf(hi, __ldg(Wq + i * 64 + tid), accQ);
        }
        g_Hkv[n * 128 + tid] = accH;
        if (tid < 64) g_Q[n * 64 + tid] = accQ;
        __syncthreads();
    }
}

// ---------------- K4: per-edge main kernel ----------------
__global__ __launch_bounds__(128, 4) void k_edge(const float* __restrict__ coord,
                                                 const int* __restrict__ row,
                                                 const int* __restrict__ col,
                                                 const float* __restrict__ eattr,
                                                 const float* __restrict__ Wkv,
                                                 const float* __restrict__ W1,
                                                 const float* __restrict__ b1,
                                                 const float* __restrict__ W2,
                                                 float* __restrict__ att) {
    // transposed weight slices: rows of 16 contiguous floats per output col
    __shared__ float sWr[128 * 16];   // sWr[j2*16+i] = Wkv[i][j2]        (radial rows 0..15)
    __shared__ float sWe[128 * 16];   // sWe[j2*16+i] = Wkv[80+i][j2]     (edge_attr rows)
    __shared__ float sW1[64 * 64];    // sW1[m*64+j] = W1[j][m]
    __shared__ float sW2[64 * 4];
    __shared__ float sb1[64];
    __shared__ float sInv[16];

    int tid = threadIdx.x;
    for (int idx = tid; idx < 128 * 16; idx += 128) {
        int j2 = idx >> 4, i = idx & 15;
        sWr[idx] = Wkv[i * 128 + j2];
        sWe[idx] = Wkv[(80 + i) * 128 + j2];
    }
    for (int idx = tid; idx < 64 * 64; idx += 128) {
        int m = idx >> 6, j = idx & 63;
        sW1[idx] = W1[j * 64 + m];
    }
    for (int idx = tid; idx < 256; idx += 128) sW2[idx] = W2[idx];
    if (tid < 64) sb1[tid] = b1[tid];
    if (tid < 16) sInv[tid] = g_invn[tid];
    __syncthreads();

    int stride = gridDim.x * blockDim.x;
    for (int e = blockIdx.x * blockDim.x + tid; e < EE; e += stride) {
        int r = row[e], c = col[e];

        // radial (normalized)
        const float4* pr = (const float4*)(coord + r * 12);
        const float4* pc = (const float4*)(coord + c * 12);
        float4 u0 = pr[0], u1 = pr[1], u2 = pr[2];
        float4 w0 = pc[0], w1 = pc[1], w2 = pc[2];
        float d[12] = {u0.x - w0.x, u0.y - w0.y, u0.z - w0.z, u0.w - w0.w,
                       u1.x - w1.x, u1.y - w1.y, u1.z - w1.z, u1.w - w1.w,
                       u2.x - w2.x, u2.y - w2.y, u2.z - w2.z, u2.w - w2.w};
        float rad[16];
#pragma unroll
        for (int a = 0; a < 4; a++)
#pragma unroll
            for (int b = 0; b < 4; b++)
                rad[a*4+b] = (d[a*3+0]*d[b*3+0] + d[a*3+1]*d[b*3+1] + d[a*3+2]*d[b*3+2])
                             * sInv[a*4+b];

        float eav[16];
        {
            const float4* pe = (const float4*)(eattr + e * 16);
            float4 e0 = pe[0], e1 = pe[1], e2 = pe[2], e3 = pe[3];
            eav[0]=e0.x; eav[1]=e0.y; eav[2]=e0.z; eav[3]=e0.w;
            eav[4]=e1.x; eav[5]=e1.y; eav[6]=e1.z; eav[7]=e1.w;
            eav[8]=e2.x; eav[9]=e2.y; eav[10]=e2.z; eav[11]=e2.w;
            eav[12]=e3.x; eav[13]=e3.y; eav[14]=e3.z; eav[15]=e3.w;
        }

        const float*  qp = g_Q + r * 64;
        const float2* hp = (const float2*)(g_Hkv + c * 128);

        float alpha = 0.0f;
#pragma unroll 2
        for (int j = 0; j < 64; j++) {
            const float* wrk = sWr + 32 * j;   // cols 2j (k) and 2j+1 (v)
            const float* wek = sWe + 32 * j;
            float kk = 0.0f, vv = 0.0f;
#pragma unroll
            for (int i = 0; i < 16; i++) {
                kk = fmaf(rad[i], wrk[i],      kk);
                vv = fmaf(rad[i], wrk[16 + i], vv);
            }
#pragma unroll
            for (int i = 0; i < 16; i++) {
                kk = fmaf(eav[i], wek[i],      kk);
                vv = fmaf(eav[i], wek[16 + i], vv);
            }
            float2 hv = hp[j];
            kk += hv.x;
            vv += hv.y;
            alpha = fmaf(__ldg(qp + j), kk, alpha);
            g_vT[j * EE + e] = vv;             // coalesced across warp
        }

        att[e] = alpha;
        atomicMaxF(&g_segmax[r], alpha);

        // silu MLP: cv = silu(v@W1 + b1) @ W2   (v reloaded; L2/L1 hits — just written)
        float vr[64];
#pragma unroll
        for (int j = 0; j < 64; j++) vr[j] = g_vT[j * EE + e];

        float cv0 = 0.0f, cv1 = 0.0f, cv2 = 0.0f, cv3 = 0.0f;
#pragma unroll 2
        for (int m = 0; m < 64; m++) {
            const float* wm = sW1 + 64 * m;
            float t = sb1[m];
#pragma unroll
            for (int j = 0; j < 64; j++) t = fmaf(vr[j], wm[j], t);
            float s = __fdividef(t, 1.0f + __expf(-t));   // silu
            cv0 = fmaf(s, sW2[4 * m + 0], cv0);
            cv1 = fmaf(s, sW2[4 * m + 1], cv1);
            cv2 = fmaf(s, sW2[4 * m + 2], cv2);
            cv3 = fmaf(s, sW2[4 * m + 3], cv3);
        }
        *(float4*)(g_cv + 4 * e) = make_float4(cv0, cv1, cv2, cv3);
    }
}

// ---------------- K5: segment softmax (exp + sum) ----------------
__global__ void k_exp(const int* __restrict__ row, float* __restrict__ att) {
    int e = blockIdx.x * blockDim.x + threadIdx.x;
    if (e >= EE) return;
    int r = row[e];
    float ex = __expf(att[e] - g_segmax[r]);
    att[e] = ex;
    atomicAdd(&g_segsum[r], ex);
}

// ---------------- K6: aggregation ----------------
__global__ void k_agg(const float* __restrict__ coord,
                      const int* __restrict__ row, const int* __restrict__ col,
                      float* __restrict__ out) {
    int e = blockIdx.x * blockDim.x + threadIdx.x;
    if (e >= EE) return;
    int r = row[e], c = col[e];

    float* att = out + NN * 76;
    float a = att[e] / g_segsum[r];
    att[e] = a;

    // h_out[r] += a * v
    float* hout = out + r * 64;
#pragma unroll
    for (int j = 0; j < 64; j += 4) {
        float x0 = a * g_vT[(j + 0) * EE + e];
        float x1 = a * g_vT[(j + 1) * EE + e];
        float x2 = a * g_vT[(j + 2) * EE + e];
        float x3 = a * g_vT[(j + 3) * EE + e];
        redAdd4(hout + j, x0, x1, x2, x3);
    }

    // coord_out[r] += coord_diff * (a * cv)
    float4 cv = *(const float4*)(g_cv + 4 * e);
    float s0 = a * cv.x, s1 = a * cv.y, s2 = a * cv.z, s3 = a * cv.w;

    const float4* pr = (const float4*)(coord + r * 12);
    const float4* pc = (const float4*)(coord + c * 12);
    float4 u0 = pr[0], u1 = pr[1], u2 = pr[2];
    float4 w0 = pc[0], w1 = pc[1], w2 = pc[2];
    float d0 = u0.x - w0.x, d1 = u0.y - w0.y, d2  = u0.z - w0.z, d3  = u0.w - w0.w;
    float d4 = u1.x - w1.x, d5 = u1.y - w1.y, d6  = u1.z - w1.z, d7  = u1.w - w1.w;
    float d8 = u2.x - w2.x, d9 = u2.y - w2.y, d10 = u2.z - w2.z, d11 = u2.w - w2.w;

    float* cout = out + NN * 64 + r * 12;
    redAdd4(cout + 0, d0 * s0, d1 * s0, d2 * s0,  d3 * s1);
    redAdd4(cout + 4, d4 * s1, d5 * s1, d6 * s2,  d7 * s2);
    redAdd4(cout + 8, d8 * s2, d9 * s3, d10 * s3, d11 * s3);
}

// ---------------- launch ----------------
extern "C" void kernel_launch(void* const* d_in, const int* in_sizes, int n_in,
                              void* d_out, int out_size) {
    const float* h     = (const float*)d_in[0];
    const float* coord = (const float*)d_in[1];
    const int*   row   = (const int*)  d_in[2];
    const int*   col   = (const int*)  d_in[3];
    const float* eattr = (const float*)d_in[4];
    const float* Wq    = (const float*)d_in[5];
    const float* bq    = (const float*)d_in[6];
    const float* Wkv   = (const float*)d_in[7];
    const float* bkv   = (const float*)d_in[8];
    const float* W1    = (const float*)d_in[9];
    const float* b1    = (const float*)d_in[10];
    const float* W2    = (const float*)d_in[11];
    float* out = (float*)d_out;
    float* att = out + NN * 76;

    k_init <<<(NN * 64 + 255) / 256, 256>>>(h, coord, out);
    k_sumsq<<<1184, 256>>>(coord, row, col);
    k_norm <<<1, 16>>>();
    k_node <<<592, 128>>>(h, Wq, bq, Wkv, bkv);
    k_edge <<<1184, 128>>>(coord, row, col, eattr, Wkv, W1, b1, W2, att);
    k_exp  <<<(EE + 255) / 256, 256>>>(row, att);
    k_agg  <<<(EE + 255) / 256, 256>>>(coord, row, col, out);
}

// round 15
// speedup vs baseline: 1.0054x; 1.0030x over previous
#include <cuda_runtime.h>
#include <math.h>

#define NN 50000
#define EE 800000
// feature dims
// h: 64, edge_attr: 16, radial: 16 (4x4), kv_in = 96, kv_out = 128

// ---------------- scratch (device globals; no allocation) ----------------
__device__ float g_Q[NN * 64];       // q = h@Wq + bq per node
__device__ float g_Hkv[NN * 128];    // h@Wkv[16:80] + bkv per node (interleaved k/v cols)
__device__ float g_vT[64 * EE];      // v transposed [j][e] for coalescing
__device__ float g_cv[EE * 4];       // silu(v@W1+b1)@W2 per edge (without att factor)
__device__ float g_sumsq[16];
__device__ float g_invn[16];
__device__ float g_segmax[NN];
__device__ float g_segsum[NN];

// ---------------- helpers ----------------
__device__ __forceinline__ void atomicMaxF(float* addr, float v) {
    if (v >= 0.0f) atomicMax((int*)addr, __float_as_int(v));
    else           atomicMin((unsigned int*)addr, __float_as_uint(v));
}

__device__ __forceinline__ void redAdd4(float* p, float a, float b, float c, float d) {
    asm volatile("red.global.add.v4.f32 [%0], {%1, %2, %3, %4};"
                 :: "l"(p), "f"(a), "f"(b), "f"(c), "f"(d) : "memory");
}

// ---------------- K0: init ----------------
__global__ void k_init(const float* __restrict__ h, const float* __restrict__ coord,
                       float* __restrict__ out) {
    int i = blockIdx.x * blockDim.x + threadIdx.x;
    if (i < NN * 64) out[i] = h[i];                 // h_out = h
    if (i < NN * 12) out[NN * 64 + i] = coord[i];   // coord_out = coord
    if (i < NN) { g_segmax[i] = -INFINITY; g_segsum[i] = 0.0f; }
    if (i < 16) g_sumsq[i] = 0.0f;
}

// ---------------- K1: global sum of radial^2 ----------------
__global__ void k_sumsq(const float* __restrict__ coord,
                        const int* __restrict__ row, const int* __restrict__ col) {
    __shared__ float s[16];
    if (threadIdx.x < 16) s[threadIdx.x] = 0.0f;
    __syncthreads();

    float acc[16];
#pragma unroll
    for (int t = 0; t < 16; t++) acc[t] = 0.0f;

    int stride = gridDim.x * blockDim.x;
    for (int e = blockIdx.x * blockDim.x + threadIdx.x; e < EE; e += stride) {
        int r = row[e], c = col[e];
        const float4* pr = (const float4*)(coord + r * 12);
        const float4* pc = (const float4*)(coord + c * 12);
        float4 u0 = pr[0], u1 = pr[1], u2 = pr[2];
        float4 w0 = pc[0], w1 = pc[1], w2 = pc[2];
        float d[12] = {u0.x - w0.x, u0.y - w0.y, u0.z - w0.z, u0.w - w0.w,
                       u1.x - w1.x, u1.y - w1.y, u1.z - w1.z, u1.w - w1.w,
                       u2.x - w2.x, u2.y - w2.y, u2.z - w2.z, u2.w - w2.w};
#pragma unroll
        for (int a = 0; a < 4; a++)
#pragma unroll
            for (int b = 0; b < 4; b++) {
                float rv = d[a*3+0]*d[b*3+0] + d[a*3+1]*d[b*3+1] + d[a*3+2]*d[b*3+2];
                acc[a*4+b] = fmaf(rv, rv, acc[a*4+b]);
            }
    }
#pragma unroll
    for (int t = 0; t < 16; t++) atomicAdd(&s[t], acc[t]);
    __syncthreads();
    if (threadIdx.x < 16) atomicAdd(&g_sumsq[threadIdx.x], s[threadIdx.x]);
}

// ---------------- K2: invnorm ----------------
__global__ void k_norm() {
    int i = threadIdx.x;
    if (i < 16) g_invn[i] = 1.0f / fmaxf(sqrtf(g_sumsq[i]), 1e-12f);
}

// ---------------- K3: per-node projections ----------------
// Q[n][j]   = bq[j]  + sum_i h[n][i] * Wq[i][j]              (j < 64)
// Hkv[n][j] = bkv[j] + sum_i h[n][i] * Wkv[16+i][j]          (j < 128)
__global__ __launch_bounds__(128) void k_node(const float* __restrict__ h,
                                              const float* __restrict__ Wq,
                                              const float* __restrict__ bq,
                                              const float* __restrict__ Wkv,
                                              const float* __restrict__ bkv) {
    __shared__ float sWm[64 * 128];
    __shared__ float sBkv[128];
    __shared__ float sBq[64];
    __shared__ float sh[64];

    int tid = threadIdx.x;
    for (int i = tid; i < 64 * 128; i += 128) sWm[i] = Wkv[16 * 128 + i];
    if (tid < 128) sBkv[tid] = bkv[tid];
    if (tid < 64)  sBq[tid]  = bq[tid];
    __syncthreads();

    for (int n = blockIdx.x; n < NN; n += gridDim.x) {
        if (tid < 64) sh[tid] = h[n * 64 + tid];
        __syncthreads();
        float accH = sBkv[tid];
        float accQ = (tid < 64) ? sBq[tid] : 0.0f;
#pragma unroll 8
        for (int i = 0; i < 64; i++) {
            float hi = sh[i];
            accH = fmaf(hi, sWm[i * 128 + tid], accH);
            if (tid < 64) accQ = fmaf(hi, __ldg(Wq + i * 64 + tid), accQ);
        }
        g_Hkv[n * 128 + tid] = accH;
        if (tid < 64) g_Q[n * 64 + tid] = accQ;
        __syncthreads();
    }
}

// ---------------- K4: per-edge main kernel ----------------
__global__ __launch_bounds__(128, 4) void k_edge(const float* __restrict__ coord,
                                                 const int* __restrict__ row,
                                                 const int* __restrict__ col,
                                                 const float* __restrict__ eattr,
                                                 const float* __restrict__ Wkv,
                                                 const float* __restrict__ W1,
                                                 const float* __restrict__ b1,
                                                 const float* __restrict__ W2,
                                                 float* __restrict__ att) {
    // transposed weight slices: rows of 16 contiguous floats per output col
    __shared__ float sWr[128 * 16];   // sWr[j2*16+i] = Wkv[i][j2]        (radial rows 0..15)
    __shared__ float sWe[128 * 16];   // sWe[j2*16+i] = Wkv[80+i][j2]     (edge_attr rows)
    __shared__ float sW1[64 * 64];    // sW1[m*64+j] = W1[j][m]
    __shared__ float sW2[64 * 4];
    __shared__ float sb1[64];
    __shared__ float sInv[16];

    int tid = threadIdx.x;
    for (int idx = tid; idx < 128 * 16; idx += 128) {
        int j2 = idx >> 4, i = idx & 15;
        sWr[idx] = Wkv[i * 128 + j2];
        sWe[idx] = Wkv[(80 + i) * 128 + j2];
    }
    for (int idx = tid; idx < 64 * 64; idx += 128) {
        int m = idx >> 6, j = idx & 63;
        sW1[idx] = W1[j * 64 + m];
    }
    for (int idx = tid; idx < 256; idx += 128) sW2[idx] = W2[idx];
    if (tid < 64) sb1[tid] = b1[tid];
    if (tid < 16) sInv[tid] = g_invn[tid];
    __syncthreads();

    int stride = gridDim.x * blockDim.x;
    for (int e = blockIdx.x * blockDim.x + tid; e < EE; e += stride) {
        int r = row[e], c = col[e];

        // radial (normalized)
        const float4* pr = (const float4*)(coord + r * 12);
        const float4* pc = (const float4*)(coord + c * 12);
        float4 u0 = pr[0], u1 = pr[1], u2 = pr[2];
        float4 w0 = pc[0], w1 = pc[1], w2 = pc[2];
        float d[12] = {u0.x - w0.x, u0.y - w0.y, u0.z - w0.z, u0.w - w0.w,
                       u1.x - w1.x, u1.y - w1.y, u1.z - w1.z, u1.w - w1.w,
                       u2.x - w2.x, u2.y - w2.y, u2.z - w2.z, u2.w - w2.w};
        float rad[16];
#pragma unroll
        for (int a = 0; a < 4; a++)
#pragma unroll
            for (int b = 0; b < 4; b++)
                rad[a*4+b] = (d[a*3+0]*d[b*3+0] + d[a*3+1]*d[b*3+1] + d[a*3+2]*d[b*3+2])
                             * sInv[a*4+b];

        float eav[16];
        {
            const float4* pe = (const float4*)(eattr + e * 16);
            float4 e0 = pe[0], e1 = pe[1], e2 = pe[2], e3 = pe[3];
            eav[0]=e0.x; eav[1]=e0.y; eav[2]=e0.z; eav[3]=e0.w;
            eav[4]=e1.x; eav[5]=e1.y; eav[6]=e1.z; eav[7]=e1.w;
            eav[8]=e2.x; eav[9]=e2.y; eav[10]=e2.z; eav[11]=e2.w;
            eav[12]=e3.x; eav[13]=e3.y; eav[14]=e3.z; eav[15]=e3.w;
        }

        const float*  qp = g_Q + r * 64;
        const float2* hp = (const float2*)(g_Hkv + c * 128);

        float alpha = 0.0f;
#pragma unroll 2
        for (int j = 0; j < 64; j++) {
            const float* wrk = sWr + 32 * j;   // cols 2j (k) and 2j+1 (v)
            const float* wek = sWe + 32 * j;
            float kk = 0.0f, vv = 0.0f;
#pragma unroll
            for (int i = 0; i < 16; i++) {
                kk = fmaf(rad[i], wrk[i],      kk);
                vv = fmaf(rad[i], wrk[16 + i], vv);
            }
#pragma unroll
            for (int i = 0; i < 16; i++) {
                kk = fmaf(eav[i], wek[i],      kk);
                vv = fmaf(eav[i], wek[16 + i], vv);
            }
            float2 hv = hp[j];
            kk += hv.x;
            vv += hv.y;
            alpha = fmaf(__ldg(qp + j), kk, alpha);
            g_vT[j * EE + e] = vv;             // coalesced across warp
        }

        att[e] = alpha;
        atomicMaxF(&g_segmax[r], alpha);

        // silu MLP: cv = silu(v@W1 + b1) @ W2   (v reloaded; L2/L1 hits — just written)
        float vr[64];
#pragma unroll
        for (int j = 0; j < 64; j++) vr[j] = g_vT[j * EE + e];

        float cv0 = 0.0f, cv1 = 0.0f, cv2 = 0.0f, cv3 = 0.0f;
#pragma unroll 2
        for (int m = 0; m < 64; m++) {
            const float* wm = sW1 + 64 * m;
            float t = sb1[m];
#pragma unroll
            for (int j = 0; j < 64; j++) t = fmaf(vr[j], wm[j], t);
            float s = __fdividef(t, 1.0f + __expf(-t));   // silu
            cv0 = fmaf(s, sW2[4 * m + 0], cv0);
            cv1 = fmaf(s, sW2[4 * m + 1], cv1);
            cv2 = fmaf(s, sW2[4 * m + 2], cv2);
            cv3 = fmaf(s, sW2[4 * m + 3], cv3);
        }
        *(float4*)(g_cv + 4 * e) = make_float4(cv0, cv1, cv2, cv3);
    }
}

// ---------------- K5: segment softmax (exp + sum) ----------------
__global__ void k_exp(const int* __restrict__ row, float* __restrict__ att) {
    int e = blockIdx.x * blockDim.x + threadIdx.x;
    if (e >= EE) return;
    int r = row[e];
    float ex = __expf(att[e] - g_segmax[r]);
    att[e] = ex;
    atomicAdd(&g_segsum[r], ex);
}

// ---------------- K6: aggregation ----------------
__global__ void k_agg(const float* __restrict__ coord,
                      const int* __restrict__ row, const int* __restrict__ col,
                      float* __restrict__ out) {
    int e = blockIdx.x * blockDim.x + threadIdx.x;
    if (e >= EE) return;
    int r = row[e], c = col[e];

    float* att = out + NN * 76;
    float a = att[e] / g_segsum[r];
    att[e] = a;

    // h_out[r] += a * v
    float* hout = out + r * 64;
#pragma unroll
    for (int j = 0; j < 64; j += 4) {
        float x0 = a * g_vT[(j + 0) * EE + e];
        float x1 = a * g_vT[(j + 1) * EE + e];
        float x2 = a * g_vT[(j + 2) * EE + e];
        float x3 = a * g_vT[(j + 3) * EE + e];
        redAdd4(hout + j, x0, x1, x2, x3);
    }

    // coord_out[r] += coord_diff * (a * cv)
    float4 cv = *(const float4*)(g_cv + 4 * e);
    float s0 = a * cv.x, s1 = a * cv.y, s2 = a * cv.z, s3 = a * cv.w;

    const float4* pr = (const float4*)(coord + r * 12);
    const float4* pc = (const float4*)(coord + c * 12);
    float4 u0 = pr[0], u1 = pr[1], u2 = pr[2];
    float4 w0 = pc[0], w1 = pc[1], w2 = pc[2];
    float d0 = u0.x - w0.x, d1 = u0.y - w0.y, d2  = u0.z - w0.z, d3  = u0.w - w0.w;
    float d4 = u1.x - w1.x, d5 = u1.y - w1.y, d6  = u1.z - w1.z, d7  = u1.w - w1.w;
    float d8 = u2.x - w2.x, d9 = u2.y - w2.y, d10 = u2.z - w2.z, d11 = u2.w - w2.w;

    float* cout = out + NN * 64 + r * 12;
    redAdd4(cout + 0, d0 * s0, d1 * s0, d2 * s0,  d3 * s1);
    redAdd4(cout + 4, d4 * s1, d5 * s1, d6 * s2,  d7 * s2);
    redAdd4(cout + 8, d8 * s2, d9 * s3, d10 * s3, d11 * s3);
}

// ---------------- launch ----------------
extern "C" void kernel_launch(void* const* d_in, const int* in_sizes, int n_in,
                              void* d_out, int out_size) {
    const float* h     = (const float*)d_in[0];
    const float* coord = (const float*)d_in[1];
    const int*   row   = (const int*)  d_in[2];
    const int*   col   = (const int*)  d_in[3];
    const float* eattr = (const float*)d_in[4];
    const float* Wq    = (const float*)d_in[5];
    const float* bq    = (const float*)d_in[6];
    const float* Wkv   = (const float*)d_in[7];
    const float* bkv   = (const float*)d_in[8];
    const float* W1    = (const float*)d_in[9];
    const float* b1    = (const float*)d_in[10];
    const float* W2    = (const float*)d_in[11];
    float* out = (float*)d_out;
    float* att = out + NN * 76;

    k_init <<<(NN * 64 + 255) / 256, 256>>>(h, coord, out);
    k_sumsq<<<1184, 256>>>(coord, row, col);
    k_norm <<<1, 16>>>();
    k_node <<<592, 128>>>(h, Wq, bq, Wkv, bkv);
    k_edge <<<1184, 128>>>(coord, row, col, eattr, Wkv, W1, b1, W2, att);
    k_exp  <<<(EE + 255) / 256, 256>>>(row, att);
    k_agg  <<<(EE + 255) / 256, 256>>>(coord, row, col, out);
}